// round 14
// baseline (speedup 1.0000x reference)
#include <cuda_runtime.h>

#define N_NODES 100000
#define IN_DIM  512
#define OUT_DIM 16
#define N_EDGES 3200000

#define SB 1024                                   // scan block size
#define NBLK ((N_NODES + SB - 1) / SB)            // 98 scan blocks

// Scratch (allocation-free rule: __device__ globals).
__device__ int   g_is64;                  // 1 if edge_index buffer is int64
__device__ int   g_cnt[N_NODES];          // in-degree (edges only, no self loop)
__device__ int   g_cur[N_NODES];          // scatter cursors
__device__ int   g_off[N_NODES];          // exclusive prefix of g_cnt
__device__ int   g_blksum[NBLK];          // per-block totals
__device__ int   g_sorted_src[N_EDGES];   // src ids grouped by dst
__device__ __align__(16) float g_feat[N_NODES * OUT_DIM]; // rsqrt(deg)*(x@W)

// ---------------------------------------------------------------------------
// K1: zero counters + dtype detection (thread 0)
// ---------------------------------------------------------------------------
__global__ void init_kernel(const int* __restrict__ ei32) {
    int i = blockIdx.x * blockDim.x + threadIdx.x;
    if (i < N_NODES) { g_cnt[i] = 0; g_cur[i] = 0; }
    if (i == 0) {
        int zeros = 0;
        for (int k = 0; k < 128; ++k) zeros += (ei32[2 * k + 1] == 0);
        g_is64 = (zeros > 64) ? 1 : 0;
    }
}

// ---------------------------------------------------------------------------
// K2: in-degree count, 4 edges per thread, vectorized dst loads
// ---------------------------------------------------------------------------
__global__ void count_kernel(const void* __restrict__ eiv) {
    int q = blockIdx.x * blockDim.x + threadIdx.x;     // quad index
    int e0 = q * 4;
    if (e0 >= N_EDGES) return;
    int d[4];
    if (g_is64) {
        const longlong2* dd = (const longlong2*)((const long long*)eiv + N_EDGES);
        longlong2 a = dd[q * 2];
        longlong2 b = dd[q * 2 + 1];
        d[0] = (int)a.x; d[1] = (int)a.y; d[2] = (int)b.x; d[3] = (int)b.y;
    } else {
        const int4* dd = (const int4*)((const int*)eiv + N_EDGES);
        int4 a = dd[q];
        d[0] = a.x; d[1] = a.y; d[2] = a.z; d[3] = a.w;
    }
#pragma unroll
    for (int k = 0; k < 4; ++k)
        if ((unsigned)d[k] < N_NODES) atomicAdd(&g_cnt[d[k]], 1);
}

// ---------------------------------------------------------------------------
// K3a: per-block scan (1024-chunk, smem Hillis-Steele), local-exclusive out
// ---------------------------------------------------------------------------
__global__ void __launch_bounds__(SB)
scan1_kernel() {
    __shared__ int s[SB];
    int t = threadIdx.x;
    int i = blockIdx.x * SB + t;
    int v = (i < N_NODES) ? g_cnt[i] : 0;
    s[t] = v;
    __syncthreads();
#pragma unroll
    for (int off = 1; off < SB; off <<= 1) {
        int u = (t >= off) ? s[t - off] : 0;
        __syncthreads();
        s[t] += u;
        __syncthreads();
    }
    if (i < N_NODES) g_off[i] = s[t] - v;       // local exclusive
    if (t == SB - 1) g_blksum[blockIdx.x] = s[t];
}

// ---------------------------------------------------------------------------
// K3b: add block base; cooperative load of block sums, then smem sum
// ---------------------------------------------------------------------------
__global__ void __launch_bounds__(SB)
scan23_kernel() {
    __shared__ int sums[NBLK];
    __shared__ int base;
    int t = threadIdx.x;
    if (t < NBLK) sums[t] = (t < (int)blockIdx.x) ? g_blksum[t] : 0;
    __syncthreads();
    if (t == 0) {
        int run = 0;
#pragma unroll 7
        for (int k = 0; k < NBLK; ++k) run += sums[k];
        base = run;
    }
    __syncthreads();
    int i = blockIdx.x * SB + t;
    if (i < N_NODES) g_off[i] += base;
}

// ---------------------------------------------------------------------------
// K4: fused GEMM + scale:  g_feat[i] = rsqrt(cnt[i]+1) * (x[i] @ W)
//     1 row/thread, 256 thr/block (391 blocks -> ~21 warps/SM, hides LDG
//     latency that capped R9 at 28% DRAM). W broadcast from smem as u64
//     pairs; LDS on LSU pipe dual-issues with FFMA2 on fma pipe.
// ---------------------------------------------------------------------------
__device__ __forceinline__ void ffma2(unsigned long long& d,
                                      unsigned long long a,
                                      unsigned long long b) {
    asm("fma.rn.f32x2 %0, %1, %2, %0;" : "+l"(d) : "l"(a), "l"(b));
}

__device__ __forceinline__ unsigned long long pack2(float lo, float hi) {
    unsigned long long r;
    asm("mov.b64 %0, {%1, %2};" : "=l"(r) : "f"(lo), "f"(hi));
    return r;
}

__global__ void __launch_bounds__(256)
gemm_scale_kernel(const float* __restrict__ x,
                  const float* __restrict__ W) {
    __shared__ unsigned long long Ws[IN_DIM * 8];   // 32 KB
    const unsigned long long* W2 = (const unsigned long long*)W;
    for (int i = threadIdx.x; i < IN_DIM * 8; i += blockDim.x) Ws[i] = W2[i];
    __syncthreads();

    int row = blockIdx.x * blockDim.x + threadIdx.x;
    if (row >= N_NODES) return;

    unsigned long long acc2[8];
#pragma unroll
    for (int j = 0; j < 8; ++j) acc2[j] = 0ull;

    const float4* xp = (const float4*)(x + (size_t)row * IN_DIM);

#pragma unroll 4
    for (int k8 = 0; k8 < IN_DIM / 8; ++k8) {
        float4 a = xp[2 * k8];
        float4 b = xp[2 * k8 + 1];
        float xv[8] = {a.x, a.y, a.z, a.w, b.x, b.y, b.z, b.w};
#pragma unroll
        for (int kk = 0; kk < 8; ++kk) {
            int kbase = (k8 * 8 + kk) * 8;
            unsigned long long x2 = pack2(xv[kk], xv[kk]);
#pragma unroll
            for (int j = 0; j < 8; ++j) ffma2(acc2[j], x2, Ws[kbase + j]);
        }
    }

    float dinv = rsqrtf((float)(g_cnt[row] + 1));
    float vals[16];
#pragma unroll
    for (int j = 0; j < 8; ++j) {
        float2 p = *(float2*)&acc2[j];
        vals[2 * j]     = p.x * dinv;
        vals[2 * j + 1] = p.y * dinv;
    }
    float4* gp = (float4*)(g_feat + (size_t)row * OUT_DIM);
#pragma unroll
    for (int q = 0; q < 4; ++q)
        gp[q] = make_float4(vals[4 * q], vals[4 * q + 1],
                            vals[4 * q + 2], vals[4 * q + 3]);
}

// ---------------------------------------------------------------------------
// K5: counting-sort scatter: group src ids by dst (reads edges directly)
// ---------------------------------------------------------------------------
__global__ void sort_scatter_kernel(const void* __restrict__ eiv) {
    int e = blockIdx.x * blockDim.x + threadIdx.x;
    if (e >= N_EDGES) return;
    int s, d;
    if (g_is64) {
        const long long* ei = (const long long*)eiv;
        s = (int)ei[e];
        d = (int)ei[e + N_EDGES];
    } else {
        const int* ei = (const int*)eiv;
        s = ei[e];
        d = ei[e + N_EDGES];
    }
    if ((unsigned)s >= N_NODES) s = 0;          // defensive
    if ((unsigned)d >= N_NODES) return;         // defensive
    int p = g_off[d] + atomicAdd(&g_cur[d], 1);
    if ((unsigned)p < N_EDGES)                  // defensive
        g_sorted_src[p] = s;
}

// ---------------------------------------------------------------------------
// K6: gather + self-loop + dinv + bias. One warp per node, 2 edges per iter
//     (16 lanes = one contiguous 64B g_feat row each).
// ---------------------------------------------------------------------------
__global__ void __launch_bounds__(256)
gather_kernel(const float* __restrict__ b, float* __restrict__ out) {
    int warp = (blockIdx.x * blockDim.x + threadIdx.x) >> 5;
    if (warp >= N_NODES) return;
    int lane = threadIdx.x & 31;
    int half = lane >> 4;        // 0 or 1: which edge of the pair
    int sub  = lane & 15;        // feature index

    int cnt   = g_cnt[warp];
    int start = g_off[warp];

    float acc = 0.0f;
    for (int j = half; j < cnt; j += 2) {
        int s = g_sorted_src[start + j];
        acc += g_feat[(size_t)s * OUT_DIM + sub];
    }
    acc += __shfl_down_sync(0xFFFFFFFFu, acc, 16);

    if (lane < 16) {
        float dinv = rsqrtf((float)(cnt + 1));
        float v = (acc + g_feat[(size_t)warp * OUT_DIM + lane]) * dinv
                  + __ldg(&b[lane]);
        out[(size_t)warp * OUT_DIM + lane] = v;
    }
}

// ---------------------------------------------------------------------------
extern "C" void kernel_launch(void* const* d_in, const int* in_sizes, int n_in,
                              void* d_out, int out_size) {
    const float* x  = (const float*)d_in[0];
    const void*  ei = d_in[1];                  // [2, E] int32 OR int64
    const float* W  = (const float*)d_in[2];
    const float* b  = (const float*)d_in[3];
    float* out = (float*)d_out;

    (void)in_sizes; (void)n_in; (void)out_size;

    init_kernel<<<(N_NODES + 255) / 256, 256>>>((const int*)ei);        // idx0
    count_kernel<<<(N_EDGES / 4 + 255) / 256, 256>>>(ei);               // idx1
    scan1_kernel<<<NBLK, SB>>>();                                       // idx2
    gemm_scale_kernel<<<(N_NODES + 255) / 256, 256>>>(x, W);            // idx3 (profiled)
    scan23_kernel<<<NBLK, SB>>>();                                      // idx4
    sort_scatter_kernel<<<(N_EDGES + 255) / 256, 256>>>(ei);            // idx5
    gather_kernel<<<(N_NODES * 32 + 255) / 256, 256>>>(b, out);         // idx6
}

// round 15
// speedup vs baseline: 1.0834x; 1.0834x over previous
#include <cuda_runtime.h>

#define N_NODES 100000
#define IN_DIM  512
#define OUT_DIM 16
#define N_EDGES 3200000

#define SB 1024                                   // scan block size
#define NBLK ((N_NODES + SB - 1) / SB)            // 98 scan blocks

// Scratch (allocation-free rule: __device__ globals).
__device__ int   g_is64;                  // 1 if edge_index buffer is int64
__device__ int   g_cnt[N_NODES];          // in-degree (edges only, no self loop)
__device__ int   g_cur[N_NODES];          // scatter cursors
__device__ int   g_off[N_NODES];          // exclusive prefix of g_cnt
__device__ int   g_blksum[NBLK];          // per-block totals
__device__ int   g_sorted_src[N_EDGES];   // src ids grouped by dst
__device__ __align__(16) float g_feat[N_NODES * OUT_DIM]; // rsqrt(deg)*(x@W)

// ---------------------------------------------------------------------------
// K1: zero counters + dtype detection (thread 0)
// ---------------------------------------------------------------------------
__global__ void init_kernel(const int* __restrict__ ei32) {
    int i = blockIdx.x * blockDim.x + threadIdx.x;
    if (i < N_NODES) { g_cnt[i] = 0; g_cur[i] = 0; }
    if (i == 0) {
        int zeros = 0;
        for (int k = 0; k < 128; ++k) zeros += (ei32[2 * k + 1] == 0);
        g_is64 = (zeros > 64) ? 1 : 0;
    }
}

// ---------------------------------------------------------------------------
// K2: in-degree count, 4 edges per thread, vectorized dst loads
// ---------------------------------------------------------------------------
__global__ void count_kernel(const void* __restrict__ eiv) {
    int q = blockIdx.x * blockDim.x + threadIdx.x;     // quad index
    int e0 = q * 4;
    if (e0 >= N_EDGES) return;
    int d[4];
    if (g_is64) {
        const longlong2* dd = (const longlong2*)((const long long*)eiv + N_EDGES);
        longlong2 a = dd[q * 2];
        longlong2 b = dd[q * 2 + 1];
        d[0] = (int)a.x; d[1] = (int)a.y; d[2] = (int)b.x; d[3] = (int)b.y;
    } else {
        const int4* dd = (const int4*)((const int*)eiv + N_EDGES);
        int4 a = dd[q];
        d[0] = a.x; d[1] = a.y; d[2] = a.z; d[3] = a.w;
    }
#pragma unroll
    for (int k = 0; k < 4; ++k)
        if ((unsigned)d[k] < N_NODES) atomicAdd(&g_cnt[d[k]], 1);
}

// ---------------------------------------------------------------------------
// K3a: per-block scan (1024-chunk, smem Hillis-Steele), local-exclusive out
// ---------------------------------------------------------------------------
__global__ void __launch_bounds__(SB)
scan1_kernel() {
    __shared__ int s[SB];
    int t = threadIdx.x;
    int i = blockIdx.x * SB + t;
    int v = (i < N_NODES) ? g_cnt[i] : 0;
    s[t] = v;
    __syncthreads();
#pragma unroll
    for (int off = 1; off < SB; off <<= 1) {
        int u = (t >= off) ? s[t - off] : 0;
        __syncthreads();
        s[t] += u;
        __syncthreads();
    }
    if (i < N_NODES) g_off[i] = s[t] - v;       // local exclusive
    if (t == SB - 1) g_blksum[blockIdx.x] = s[t];
}

// ---------------------------------------------------------------------------
// K3b: add block base; cooperative load of block sums, then smem sum
// ---------------------------------------------------------------------------
__global__ void __launch_bounds__(SB)
scan23_kernel() {
    __shared__ int sums[NBLK];
    __shared__ int base;
    int t = threadIdx.x;
    if (t < NBLK) sums[t] = (t < (int)blockIdx.x) ? g_blksum[t] : 0;
    __syncthreads();
    if (t == 0) {
        int run = 0;
#pragma unroll 7
        for (int k = 0; k < NBLK; ++k) run += sums[k];
        base = run;
    }
    __syncthreads();
    int i = blockIdx.x * SB + t;
    if (i < N_NODES) g_off[i] += base;
}

// ---------------------------------------------------------------------------
// K4: fused GEMM + scale:  g_feat[i] = rsqrt(cnt[i]+1) * (x[i] @ W)
//     2 rows/thread, 128 thr/block (391 blocks). W broadcast from smem via
//     LDS.128 (ulonglong2) and reused across 2 rows: LSU:FMA ~ 1:3.6 so the
//     fma pipe, not LSU, is the binder (R14 was LSU-bound at L1=79%).
// ---------------------------------------------------------------------------
__device__ __forceinline__ void ffma2(unsigned long long& d,
                                      unsigned long long a,
                                      unsigned long long b) {
    asm("fma.rn.f32x2 %0, %1, %2, %0;" : "+l"(d) : "l"(a), "l"(b));
}

__device__ __forceinline__ unsigned long long pack2(float v) {
    unsigned long long r;
    asm("mov.b64 %0, {%1, %1};" : "=l"(r) : "f"(v));
    return r;
}

__global__ void __launch_bounds__(128)
gemm_scale_kernel(const float* __restrict__ x,
                  const float* __restrict__ W) {
    // W[512][16] row-major -> per k: 4 ulonglong2 (16 floats). 32 KB total.
    __shared__ ulonglong2 Ws[IN_DIM * 4];
    const ulonglong2* W4 = (const ulonglong2*)W;
    for (int i = threadIdx.x; i < IN_DIM * 4; i += blockDim.x) Ws[i] = W4[i];
    __syncthreads();

    int t = blockIdx.x * blockDim.x + threadIdx.x;
    int row0 = t * 2;
    if (row0 >= N_NODES) return;

    unsigned long long acc0[8], acc1[8];
#pragma unroll
    for (int j = 0; j < 8; ++j) { acc0[j] = 0ull; acc1[j] = 0ull; }

    const float4* xpa = (const float4*)(x + (size_t)row0 * IN_DIM);
    const float4* xpb = (const float4*)(x + (size_t)(row0 + 1) * IN_DIM);

#pragma unroll 2
    for (int k8 = 0; k8 < IN_DIM / 8; ++k8) {
        float4 a0 = xpa[2 * k8];
        float4 a1 = xpa[2 * k8 + 1];
        float4 b0 = xpb[2 * k8];
        float4 b1 = xpb[2 * k8 + 1];
        float xa[8] = {a0.x, a0.y, a0.z, a0.w, a1.x, a1.y, a1.z, a1.w};
        float xb[8] = {b0.x, b0.y, b0.z, b0.w, b1.x, b1.y, b1.z, b1.w};
#pragma unroll
        for (int kk = 0; kk < 8; ++kk) {
            int kb = (k8 * 8 + kk) * 4;
            ulonglong2 w0 = Ws[kb];
            ulonglong2 w1 = Ws[kb + 1];
            ulonglong2 w2 = Ws[kb + 2];
            ulonglong2 w3 = Ws[kb + 3];
            unsigned long long xa2 = pack2(xa[kk]);
            unsigned long long xb2 = pack2(xb[kk]);
            ffma2(acc0[0], xa2, w0.x); ffma2(acc1[0], xb2, w0.x);
            ffma2(acc0[1], xa2, w0.y); ffma2(acc1[1], xb2, w0.y);
            ffma2(acc0[2], xa2, w1.x); ffma2(acc1[2], xb2, w1.x);
            ffma2(acc0[3], xa2, w1.y); ffma2(acc1[3], xb2, w1.y);
            ffma2(acc0[4], xa2, w2.x); ffma2(acc1[4], xb2, w2.x);
            ffma2(acc0[5], xa2, w2.y); ffma2(acc1[5], xb2, w2.y);
            ffma2(acc0[6], xa2, w3.x); ffma2(acc1[6], xb2, w3.x);
            ffma2(acc0[7], xa2, w3.y); ffma2(acc1[7], xb2, w3.y);
        }
    }

#pragma unroll
    for (int r = 0; r < 2; ++r) {
        int row = row0 + r;
        const unsigned long long* acc = r ? acc1 : acc0;
        float dinv = rsqrtf((float)(g_cnt[row] + 1));
        float vals[16];
#pragma unroll
        for (int j = 0; j < 8; ++j) {
            float2 p = *(float2*)&acc[j];
            vals[2 * j]     = p.x * dinv;
            vals[2 * j + 1] = p.y * dinv;
        }
        float4* gp = (float4*)(g_feat + (size_t)row * OUT_DIM);
#pragma unroll
        for (int q = 0; q < 4; ++q)
            gp[q] = make_float4(vals[4 * q], vals[4 * q + 1],
                                vals[4 * q + 2], vals[4 * q + 3]);
    }
}

// ---------------------------------------------------------------------------
// K5: counting-sort scatter: group src ids by dst (reads edges directly)
// ---------------------------------------------------------------------------
__global__ void sort_scatter_kernel(const void* __restrict__ eiv) {
    int e = blockIdx.x * blockDim.x + threadIdx.x;
    if (e >= N_EDGES) return;
    int s, d;
    if (g_is64) {
        const long long* ei = (const long long*)eiv;
        s = (int)ei[e];
        d = (int)ei[e + N_EDGES];
    } else {
        const int* ei = (const int*)eiv;
        s = ei[e];
        d = ei[e + N_EDGES];
    }
    if ((unsigned)s >= N_NODES) s = 0;          // defensive
    if ((unsigned)d >= N_NODES) return;         // defensive
    int p = g_off[d] + atomicAdd(&g_cur[d], 1);
    if ((unsigned)p < N_EDGES)                  // defensive
        g_sorted_src[p] = s;
}

// ---------------------------------------------------------------------------
// K6: gather + self-loop + dinv + bias. One warp per node, 2 edges per iter
//     (16 lanes = one contiguous 64B g_feat row each).
// ---------------------------------------------------------------------------
__global__ void __launch_bounds__(256)
gather_kernel(const float* __restrict__ b, float* __restrict__ out) {
    int warp = (blockIdx.x * blockDim.x + threadIdx.x) >> 5;
    if (warp >= N_NODES) return;
    int lane = threadIdx.x & 31;
    int half = lane >> 4;        // 0 or 1: which edge of the pair
    int sub  = lane & 15;        // feature index

    int cnt   = g_cnt[warp];
    int start = g_off[warp];

    float acc = 0.0f;
    for (int j = half; j < cnt; j += 2) {
        int s = g_sorted_src[start + j];
        acc += g_feat[(size_t)s * OUT_DIM + sub];
    }
    acc += __shfl_down_sync(0xFFFFFFFFu, acc, 16);

    if (lane < 16) {
        float dinv = rsqrtf((float)(cnt + 1));
        float v = (acc + g_feat[(size_t)warp * OUT_DIM + lane]) * dinv
                  + __ldg(&b[lane]);
        out[(size_t)warp * OUT_DIM + lane] = v;
    }
}

// ---------------------------------------------------------------------------
extern "C" void kernel_launch(void* const* d_in, const int* in_sizes, int n_in,
                              void* d_out, int out_size) {
    const float* x  = (const float*)d_in[0];
    const void*  ei = d_in[1];                  // [2, E] int32 OR int64
    const float* W  = (const float*)d_in[2];
    const float* b  = (const float*)d_in[3];
    float* out = (float*)d_out;

    (void)in_sizes; (void)n_in; (void)out_size;

    init_kernel<<<(N_NODES + 255) / 256, 256>>>((const int*)ei);        // idx0
    count_kernel<<<(N_EDGES / 4 + 255) / 256, 256>>>(ei);               // idx1
    scan1_kernel<<<NBLK, SB>>>();                                       // idx2
    gemm_scale_kernel<<<(N_NODES / 2 + 127) / 128, 128>>>(x, W);        // idx3 (profiled)
    scan23_kernel<<<NBLK, SB>>>();                                      // idx4
    sort_scatter_kernel<<<(N_EDGES + 255) / 256, 256>>>(ei);            // idx5
    gather_kernel<<<(N_NODES * 32 + 255) / 256, 256>>>(b, out);         // idx6
}

// round 16
// speedup vs baseline: 1.1855x; 1.0942x over previous
#include <cuda_runtime.h>

#define N_NODES 100000
#define IN_DIM  512
#define OUT_DIM 16
#define N_EDGES 3200000

#define SB 1024                                   // scan block size
#define NBLK ((N_NODES + SB - 1) / SB)            // 98 scan blocks

// GEMM tiling
#define KT      32                                // K-tile
#define NTILES  (IN_DIM / KT)                     // 16
#define TROWS   256                               // rows per block
#define XSTRIDE 36                                // staged row stride (floats)
#define XBUF    (TROWS * XSTRIDE)                 // floats per buffer
#define W_SMEM_BYTES  (IN_DIM * 16 * 4)           // 32 KB
#define GEMM_SMEM (W_SMEM_BYTES + 2 * XBUF * 4)   // 32K + 73728 = 106496

// Scratch (allocation-free rule: __device__ globals).
__device__ int   g_is64;                  // 1 if edge_index buffer is int64
__device__ int   g_cnt[N_NODES];          // in-degree (edges only, no self loop)
__device__ int   g_cur[N_NODES];          // scatter cursors
__device__ int   g_off[N_NODES];          // exclusive prefix of g_cnt
__device__ int   g_blksum[NBLK];          // per-block totals
__device__ int   g_sorted_src[N_EDGES];   // src ids grouped by dst
__device__ __align__(16) float g_feat[N_NODES * OUT_DIM]; // rsqrt(deg)*(x@W)

// ---------------------------------------------------------------------------
// K1: zero counters + dtype detection (thread 0)
// ---------------------------------------------------------------------------
__global__ void init_kernel(const int* __restrict__ ei32) {
    int i = blockIdx.x * blockDim.x + threadIdx.x;
    if (i < N_NODES) { g_cnt[i] = 0; g_cur[i] = 0; }
    if (i == 0) {
        int zeros = 0;
        for (int k = 0; k < 128; ++k) zeros += (ei32[2 * k + 1] == 0);
        g_is64 = (zeros > 64) ? 1 : 0;
    }
}

// ---------------------------------------------------------------------------
// K2: in-degree count, 4 edges per thread, vectorized dst loads
// ---------------------------------------------------------------------------
__global__ void count_kernel(const void* __restrict__ eiv) {
    int q = blockIdx.x * blockDim.x + threadIdx.x;     // quad index
    int e0 = q * 4;
    if (e0 >= N_EDGES) return;
    int d[4];
    if (g_is64) {
        const longlong2* dd = (const longlong2*)((const long long*)eiv + N_EDGES);
        longlong2 a = dd[q * 2];
        longlong2 b = dd[q * 2 + 1];
        d[0] = (int)a.x; d[1] = (int)a.y; d[2] = (int)b.x; d[3] = (int)b.y;
    } else {
        const int4* dd = (const int4*)((const int*)eiv + N_EDGES);
        int4 a = dd[q];
        d[0] = a.x; d[1] = a.y; d[2] = a.z; d[3] = a.w;
    }
#pragma unroll
    for (int k = 0; k < 4; ++k)
        if ((unsigned)d[k] < N_NODES) atomicAdd(&g_cnt[d[k]], 1);
}

// ---------------------------------------------------------------------------
// K3a: per-block scan (1024-chunk, smem Hillis-Steele), local-exclusive out
// ---------------------------------------------------------------------------
__global__ void __launch_bounds__(SB)
scan1_kernel() {
    __shared__ int s[SB];
    int t = threadIdx.x;
    int i = blockIdx.x * SB + t;
    int v = (i < N_NODES) ? g_cnt[i] : 0;
    s[t] = v;
    __syncthreads();
#pragma unroll
    for (int off = 1; off < SB; off <<= 1) {
        int u = (t >= off) ? s[t - off] : 0;
        __syncthreads();
        s[t] += u;
        __syncthreads();
    }
    if (i < N_NODES) g_off[i] = s[t] - v;       // local exclusive
    if (t == SB - 1) g_blksum[blockIdx.x] = s[t];
}

// ---------------------------------------------------------------------------
// K3b: add block base; cooperative load of block sums, then smem sum
// ---------------------------------------------------------------------------
__global__ void __launch_bounds__(SB)
scan23_kernel() {
    __shared__ int sums[NBLK];
    __shared__ int base;
    int t = threadIdx.x;
    if (t < NBLK) sums[t] = (t < (int)blockIdx.x) ? g_blksum[t] : 0;
    __syncthreads();
    if (t == 0) {
        int run = 0;
#pragma unroll 7
        for (int k = 0; k < NBLK; ++k) run += sums[k];
        base = run;
    }
    __syncthreads();
    int i = blockIdx.x * SB + t;
    if (i < N_NODES) g_off[i] += base;
}

// ---------------------------------------------------------------------------
// K4: fused GEMM + scale, X staged through smem (coalesced cp.async tiles).
//     R15 was L1tex-bound: per-warp LDG.128 hit 32 distinct lines (one row
//     per lane, 2KB stride) = 32 wavefronts each. Staging makes the gmem
//     side 1 wf/128B and the smem side conflict-free (stride 36 floats).
// ---------------------------------------------------------------------------
__device__ __forceinline__ void ffma2(unsigned long long& d,
                                      unsigned long long a,
                                      unsigned long long b) {
    asm("fma.rn.f32x2 %0, %1, %2, %0;" : "+l"(d) : "l"(a), "l"(b));
}

__device__ __forceinline__ unsigned long long pack2(float v) {
    unsigned long long r;
    asm("mov.b64 %0, {%1, %1};" : "=l"(r) : "f"(v));
    return r;
}

__device__ __forceinline__ void copy_tile_async(const float* __restrict__ x,
                                                float* __restrict__ dst,
                                                int rowBase, int t, int tid) {
#pragma unroll
    for (int i = 0; i < 16; ++i) {
        int f  = tid + i * 128;          // float4 id in tile (2048 total)
        int r  = f >> 3;                 // tile row
        int c4 = f & 7;                  // float4 column
        int gr = rowBase + r;
        if (gr >= N_NODES) gr = N_NODES - 1;           // clamp (dup row)
        const float* s = x + (size_t)gr * IN_DIM + t * KT + c4 * 4;
        float* d = dst + r * XSTRIDE + c4 * 4;
        unsigned int da = (unsigned int)__cvta_generic_to_shared(d);
        asm volatile("cp.async.cg.shared.global [%0], [%1], 16;"
                     :: "r"(da), "l"(s));
    }
    asm volatile("cp.async.commit_group;");
}

__global__ void __launch_bounds__(128)
gemm_scale_kernel(const float* __restrict__ x,
                  const float* __restrict__ W) {
    extern __shared__ unsigned char smem[];
    ulonglong2* Ws = (ulonglong2*)smem;                 // [IN_DIM*4], 32KB
    float* xs = (float*)(smem + W_SMEM_BYTES);          // [2][TROWS][XSTRIDE]

    int tid = threadIdx.x;
    int rowBase = blockIdx.x * TROWS;

    // W staging (plain LDG+STS) overlapped with first tile cp.async
    const ulonglong2* W4 = (const ulonglong2*)W;
    for (int i = tid; i < IN_DIM * 4; i += 128) Ws[i] = W4[i];

    copy_tile_async(x, xs, rowBase, 0, tid);

    unsigned long long acc0[8], acc1[8];
#pragma unroll
    for (int j = 0; j < 8; ++j) { acc0[j] = 0ull; acc1[j] = 0ull; }

    for (int t = 0; t < NTILES; ++t) {
        if (t + 1 < NTILES)
            copy_tile_async(x, xs + ((t + 1) & 1) * XBUF, rowBase, t + 1, tid);
        else
            asm volatile("cp.async.commit_group;");     // dummy group
        asm volatile("cp.async.wait_group 1;");
        __syncthreads();                                // tile t + W visible

        const float* xb = xs + (t & 1) * XBUF;
        const float* xr0 = xb + tid * XSTRIDE;          // row tid
        const float* xr1 = xb + (tid + 128) * XSTRIDE;  // row tid+128

#pragma unroll
        for (int k8 = 0; k8 < KT / 8; ++k8) {
            float4 a0 = *(const float4*)(xr0 + k8 * 8);
            float4 a1 = *(const float4*)(xr0 + k8 * 8 + 4);
            float4 b0 = *(const float4*)(xr1 + k8 * 8);
            float4 b1 = *(const float4*)(xr1 + k8 * 8 + 4);
            float xa[8] = {a0.x, a0.y, a0.z, a0.w, a1.x, a1.y, a1.z, a1.w};
            float xb8[8] = {b0.x, b0.y, b0.z, b0.w, b1.x, b1.y, b1.z, b1.w};
#pragma unroll
            for (int kk = 0; kk < 8; ++kk) {
                int kb = (t * KT + k8 * 8 + kk) * 4;
                ulonglong2 w0 = Ws[kb];
                ulonglong2 w1 = Ws[kb + 1];
                ulonglong2 w2 = Ws[kb + 2];
                ulonglong2 w3 = Ws[kb + 3];
                unsigned long long xa2 = pack2(xa[kk]);
                unsigned long long xb2 = pack2(xb8[kk]);
                ffma2(acc0[0], xa2, w0.x); ffma2(acc1[0], xb2, w0.x);
                ffma2(acc0[1], xa2, w0.y); ffma2(acc1[1], xb2, w0.y);
                ffma2(acc0[2], xa2, w1.x); ffma2(acc1[2], xb2, w1.x);
                ffma2(acc0[3], xa2, w1.y); ffma2(acc1[3], xb2, w1.y);
                ffma2(acc0[4], xa2, w2.x); ffma2(acc1[4], xb2, w2.x);
                ffma2(acc0[5], xa2, w2.y); ffma2(acc1[5], xb2, w2.y);
                ffma2(acc0[6], xa2, w3.x); ffma2(acc1[6], xb2, w3.x);
                ffma2(acc0[7], xa2, w3.y); ffma2(acc1[7], xb2, w3.y);
            }
        }
        __syncthreads();                                // done with buffer
    }

#pragma unroll
    for (int r = 0; r < 2; ++r) {
        int row = rowBase + tid + r * 128;
        if (row >= N_NODES) continue;
        const unsigned long long* acc = r ? acc1 : acc0;
        float dinv = rsqrtf((float)(g_cnt[row] + 1));
        float vals[16];
#pragma unroll
        for (int j = 0; j < 8; ++j) {
            float2 p = *(float2*)&acc[j];
            vals[2 * j]     = p.x * dinv;
            vals[2 * j + 1] = p.y * dinv;
        }
        float4* gp = (float4*)(g_feat + (size_t)row * OUT_DIM);
#pragma unroll
        for (int q = 0; q < 4; ++q)
            gp[q] = make_float4(vals[4 * q], vals[4 * q + 1],
                                vals[4 * q + 2], vals[4 * q + 3]);
    }
}

// ---------------------------------------------------------------------------
// K5: counting-sort scatter: group src ids by dst (reads edges directly)
// ---------------------------------------------------------------------------
__global__ void sort_scatter_kernel(const void* __restrict__ eiv) {
    int e = blockIdx.x * blockDim.x + threadIdx.x;
    if (e >= N_EDGES) return;
    int s, d;
    if (g_is64) {
        const long long* ei = (const long long*)eiv;
        s = (int)ei[e];
        d = (int)ei[e + N_EDGES];
    } else {
        const int* ei = (const int*)eiv;
        s = ei[e];
        d = ei[e + N_EDGES];
    }
    if ((unsigned)s >= N_NODES) s = 0;          // defensive
    if ((unsigned)d >= N_NODES) return;         // defensive
    int p = g_off[d] + atomicAdd(&g_cur[d], 1);
    if ((unsigned)p < N_EDGES)                  // defensive
        g_sorted_src[p] = s;
}

// ---------------------------------------------------------------------------
// K6: gather + self-loop + dinv + bias. One warp per node, 2 edges per iter
//     (16 lanes = one contiguous 64B g_feat row each).
// ---------------------------------------------------------------------------
__global__ void __launch_bounds__(256)
gather_kernel(const float* __restrict__ b, float* __restrict__ out) {
    int warp = (blockIdx.x * blockDim.x + threadIdx.x) >> 5;
    if (warp >= N_NODES) return;
    int lane = threadIdx.x & 31;
    int half = lane >> 4;        // 0 or 1: which edge of the pair
    int sub  = lane & 15;        // feature index

    int cnt   = g_cnt[warp];
    int start = g_off[warp];

    float acc = 0.0f;
    for (int j = half; j < cnt; j += 2) {
        int s = g_sorted_src[start + j];
        acc += g_feat[(size_t)s * OUT_DIM + sub];
    }
    acc += __shfl_down_sync(0xFFFFFFFFu, acc, 16);

    if (lane < 16) {
        float dinv = rsqrtf((float)(cnt + 1));
        float v = (acc + g_feat[(size_t)warp * OUT_DIM + lane]) * dinv
                  + __ldg(&b[lane]);
        out[(size_t)warp * OUT_DIM + lane] = v;
    }
}

// ---------------------------------------------------------------------------
extern "C" void kernel_launch(void* const* d_in, const int* in_sizes, int n_in,
                              void* d_out, int out_size) {
    const float* x  = (const float*)d_in[0];
    const void*  ei = d_in[1];                  // [2, E] int32 OR int64
    const float* W  = (const float*)d_in[2];
    const float* b  = (const float*)d_in[3];
    float* out = (float*)d_out;

    (void)in_sizes; (void)n_in; (void)out_size;

    cudaFuncSetAttribute(gemm_scale_kernel,
                         cudaFuncAttributeMaxDynamicSharedMemorySize,
                         GEMM_SMEM);

    init_kernel<<<(N_NODES + 255) / 256, 256>>>((const int*)ei);        // idx0
    count_kernel<<<(N_EDGES / 4 + 255) / 256, 256>>>(ei);               // idx1
    scan1_kernel<<<NBLK, SB>>>();                                       // idx2
    gemm_scale_kernel<<<(N_NODES + TROWS - 1) / TROWS, 128, GEMM_SMEM>>>(x, W); // idx3 (profiled)
    scan23_kernel<<<NBLK, SB>>>();                                      // idx4
    sort_scatter_kernel<<<(N_EDGES + 255) / 256, 256>>>(ei);            // idx5
    gather_kernel<<<(N_NODES * 32 + 255) / 256, 256>>>(b, out);         // idx6
}